// round 1
// baseline (speedup 1.0000x reference)
#include <cuda_runtime.h>

#define LMAXC 4
#define SC    25      // (LMAX+1)^2
#define RBC   12
#define RAC   11
#define DC    64
#define NPAIR 15      // (l,m>=0) pairs
#define TPB   256

typedef unsigned long long u64;

// ---------- packed f32x2 helpers (Blackwell FFMA2 path) ----------
__device__ __forceinline__ u64 pk(float lo, float hi) {
    u64 r; asm("mov.b64 %0, {%1,%2};" : "=l"(r) : "f"(lo), "f"(hi)); return r;
}
__device__ __forceinline__ void unpk(u64 v, float& lo, float& hi) {
    asm("mov.b64 {%0,%1}, %2;" : "=f"(lo), "=f"(hi) : "l"(v));
}
__device__ __forceinline__ u64 fma2(u64 a, u64 b, u64 c) {
    u64 d; asm("fma.rn.f32x2 %0, %1, %2, %3;" : "=l"(d) : "l"(a), "l"(b), "l"(c)); return d;
}
__device__ __forceinline__ u64 mul2(u64 a, u64 b) {
    u64 d; asm("mul.rn.f32x2 %0, %1, %2;" : "=l"(d) : "l"(a), "l"(b)); return d;
}
__device__ __forceinline__ u64 add2(u64 a, u64 b) {
    u64 d; asm("add.rn.f32x2 %0, %1, %2;" : "=l"(d) : "l"(a), "l"(b)); return d;
}

// ---------- device-global tables built by prep kernel (value-duplicated pairs) ----------
__device__ u64 g_P [RBC * NPAIR];   // P[l,m>=0](x_b)
__device__ u64 g_Pw[RBC * NPAIR];   // P * qw[b]
__device__ u64 g_AC[RAC * 4];       // sqrt2*cos(m*alpha_a), m=1..4
__device__ u64 g_AS[RAC * 4];       // sqrt2*sin(m*alpha_a), m=1..4

// Extract P / qw / ang tables exactly from Y, Yw (no trig):
//   Y[b,a,idx(l,m)] = P[l,|m|](x_b) * ang_m(alpha_a)
//   a=0 column: ang_0=1, ang_{m>0}=sqrt2, ang_{m<0}=0
__global__ void gtp_prep(const float* __restrict__ Y, const float* __restrict__ Yw) {
    const int t = threadIdx.x;
    const float SQ2  = 1.41421356237309504880f;
    const float ISQ2 = 0.70710678118654752440f;
    if (t < RBC * NPAIR) {
        int b = t / NPAIR, p = t % NPAIR;
        // p -> (l,m), l-major, m=0..l
        int l = 0, rem = p;
        while (rem > l) { rem -= (l + 1); ++l; }
        int m = rem;
        int sidx = l * l + l + m;
        float y0 = Y[(b * RAC) * SC + sidx];          // a = 0
        float P  = (m > 0) ? y0 * ISQ2 : y0;
        float qw = Yw[(b * RAC) * SC] / Y[(b * RAC) * SC];   // Y[b,0,0] = const > 0
        g_P [t] = pk(P, P);
        float pw = P * qw;
        g_Pw[t] = pk(pw, pw);
    } else if (t >= 192 && t < 192 + RAC * 4) {
        int u = t - 192;
        int a = u / 4, m = (u % 4) + 1;
        const int b0 = RBC / 2;                        // mid Gauss node: sin(beta) ~ 1
        float denom = Y[(b0 * RAC) * SC + m * m + 2 * m];        // sqrt2 * P[m][m](b0)
        float ac = Y[(b0 * RAC + a) * SC + m * m + 2 * m] / denom;   // cos(m*alpha_a)
        float as = Y[(b0 * RAC + a) * SC + m * m]         / denom;   // sin(m*alpha_a)
        g_AC[a * 4 + (m - 1)] = pk(ac * SQ2, ac * SQ2);
        g_AS[a * 4 + (m - 1)] = pk(as * SQ2, as * SQ2);
    }
}

// c[s] = sum_d x[d] * W[d][s] for two packed rows (x, x+DC)
__device__ __forceinline__ void proj_c(const float* __restrict__ x,
                                       const u64* __restrict__ sW, u64 (&c)[SC]) {
    #pragma unroll
    for (int s = 0; s < SC; s++) c[s] = 0ull;
    const float4* xa = (const float4*)(x);
    const float4* xb = (const float4*)(x + DC);
    #pragma unroll 4
    for (int d4 = 0; d4 < DC / 4; d4++) {
        float4 A = xa[d4], B = xb[d4];
        u64 xv[4] = { pk(A.x, B.x), pk(A.y, B.y), pk(A.z, B.z), pk(A.w, B.w) };
        #pragma unroll
        for (int j = 0; j < 4; j++) {
            const u64* w = &sW[(d4 * 4 + j) * 26];
            #pragma unroll
            for (int s = 0; s < SC; s++) c[s] = fma2(xv[j], w[s], c[s]);
        }
    }
}

__global__ void __launch_bounds__(TPB, 1)
gtp_main(const float* __restrict__ x1, const float* __restrict__ x2,
         const float* __restrict__ W1, const float* __restrict__ W2,
         float* __restrict__ out, int nrows) {
    __shared__ u64 sW1[DC * 26];
    __shared__ u64 sW2[DC * 26];
    __shared__ u64 sP [RBC * NPAIR];
    __shared__ u64 sPw[RBC * NPAIR];
    __shared__ u64 sAC[RAC * 4];
    __shared__ u64 sAS[RAC * 4];

    const int tid = threadIdx.x;
    for (int k = tid; k < DC * SC; k += TPB) {
        int d = k / SC, s = k % SC;
        float w = W1[k]; sW1[d * 26 + s] = pk(w, w);
        w = W2[k];       sW2[d * 26 + s] = pk(w, w);
    }
    for (int k = tid; k < DC; k += TPB) { sW1[k * 26 + 25] = 0ull; sW2[k * 26 + 25] = 0ull; }
    if (tid < RBC * NPAIR) { sP[tid] = g_P[tid]; sPw[tid] = g_Pw[tid]; }
    if (tid < RAC * 4)     { sAC[tid] = g_AC[tid]; sAS[tid] = g_AS[tid]; }
    __syncthreads();

    const long long pr = (long long)blockIdx.x * TPB + tid;   // row pair index
    if (2 * pr >= nrows) return;
    const long long r0 = 2 * pr;

    u64 c1[SC], c2[SC];
    proj_c(x1 + r0 * DC, sW1, c1);
    proj_c(x2 + r0 * DC, sW2, c2);

    u64 acc[SC];
    #pragma unroll
    for (int s = 0; s < SC; s++) acc[s] = 0ull;

    #pragma unroll 1
    for (int b = 0; b < RBC; b++) {
        const u64* Pb  = &sP [b * NPAIR];
        const u64* Pwb = &sPw[b * NPAIR];

        // F stage: F[4+m] = sum_l c[idx(l,+m)]*P[l,m,b] ; F[4-m] uses c[idx(l,-m)]
        u64 F1[9], F2[9];
        #pragma unroll
        for (int i = 0; i < 9; i++) { F1[i] = 0ull; F2[i] = 0ull; }
        #pragma unroll
        for (int l = 0; l <= LMAXC; l++) {
            #pragma unroll
            for (int m = 0; m <= l; m++) {
                const int p  = l * (l + 1) / 2 + m;
                const int ip = l * l + l + m;
                const int in_ = l * l + l - m;
                u64 P = Pb[p];
                F1[4 + m] = fma2(c1[ip], P, F1[4 + m]);
                F2[4 + m] = fma2(c2[ip], P, F2[4 + m]);
                if (m > 0) {
                    F1[4 - m] = fma2(c1[in_], P, F1[4 - m]);
                    F2[4 - m] = fma2(c2[in_], P, F2[4 - m]);
                }
            }
        }

        // alpha loop: evaluate g1,g2, product, project back onto ang_m
        u64 H[9];
        #pragma unroll
        for (int i = 0; i < 9; i++) H[i] = 0ull;
        #pragma unroll
        for (int a = 0; a < RAC; a++) {
            u64 g1 = F1[4], g2 = F2[4];
            #pragma unroll
            for (int m = 1; m <= 4; m++) {
                u64 ac  = sAC[a * 4 + m - 1];
                u64 as_ = sAS[a * 4 + m - 1];
                g1 = fma2(F1[4 + m], ac , g1);
                g2 = fma2(F2[4 + m], ac , g2);
                g1 = fma2(F1[4 - m], as_, g1);
                g2 = fma2(F2[4 - m], as_, g2);
            }
            u64 h = mul2(g1, g2);
            H[4] = add2(H[4], h);
            #pragma unroll
            for (int m = 1; m <= 4; m++) {
                H[4 + m] = fma2(h, sAC[a * 4 + m - 1], H[4 + m]);
                H[4 - m] = fma2(h, sAS[a * 4 + m - 1], H[4 - m]);
            }
        }

        // out stage: acc[idx(l,±m)] += H[4±m] * P[l,m,b]*qw[b]
        #pragma unroll
        for (int l = 0; l <= LMAXC; l++) {
            #pragma unroll
            for (int m = 0; m <= l; m++) {
                const int p = l * (l + 1) / 2 + m;
                u64 Pw = Pwb[p];
                acc[l * l + l + m] = fma2(H[4 + m], Pw, acc[l * l + l + m]);
                if (m > 0)
                    acc[l * l + l - m] = fma2(H[4 - m], Pw, acc[l * l + l - m]);
            }
        }
    }

    float* o = out + r0 * SC;   // rows r0 and r0+1 are 50 consecutive floats
    #pragma unroll
    for (int s = 0; s < SC; s++) {
        float va, vb; unpk(acc[s], va, vb);
        o[s]      = va;
        o[SC + s] = vb;
    }
}

extern "C" void kernel_launch(void* const* d_in, const int* in_sizes, int n_in,
                              void* d_out, int out_size) {
    const float* x1 = (const float*)d_in[0];
    const float* x2 = (const float*)d_in[1];
    const float* W1 = (const float*)d_in[2];
    const float* W2 = (const float*)d_in[3];
    const float* Y  = (const float*)d_in[4];
    const float* Yw = (const float*)d_in[5];
    float* out = (float*)d_out;

    const int nrows = in_sizes[0] / DC;           // 131072
    const int pairs = (nrows + 1) / 2;            // 65536
    const int grid  = (pairs + TPB - 1) / TPB;    // 256

    gtp_prep<<<1, 256>>>(Y, Yw);
    gtp_main<<<grid, TPB>>>(x1, x2, W1, W2, out, nrows);
}

// round 2
// speedup vs baseline: 1.3404x; 1.3404x over previous
#include <cuda_runtime.h>

#define SC   25     // (LMAX+1)^2
#define RBC  12
#define RAC  11
#define DC   64
#define NP   15     // (l, m>=0) pairs
#define TPB  128

typedef unsigned long long u64;

// ---------- packed f32x2 helpers (Blackwell FFMA2 path) ----------
__device__ __forceinline__ u64 pk(float lo, float hi) {
    u64 r; asm("mov.b64 %0, {%1,%2};" : "=l"(r) : "f"(lo), "f"(hi)); return r;
}
__device__ __forceinline__ void unpk(u64 v, float& lo, float& hi) {
    asm("mov.b64 {%0,%1}, %2;" : "=f"(lo), "=f"(hi) : "l"(v));
}
__device__ __forceinline__ u64 fma2(u64 a, u64 b, u64 c) {
    u64 d; asm("fma.rn.f32x2 %0, %1, %2, %3;" : "=l"(d) : "l"(a), "l"(b), "l"(c)); return d;
}

// (l,m) pair tables, p = l(l+1)/2 + m, m = 0..l
static __device__ const int c_ip[NP] = {0, 2,3, 6,7,8, 12,13,14,15, 20,21,22,23,24};
static __device__ const int c_in[NP] = {0, 2,1, 6,5,4, 12,11,10, 9, 20,19,18,17,16};
static __device__ const int c_m [NP] = {0, 0,1, 0,1,2,  0, 1, 2, 3,  0, 1, 2, 3, 4};

__global__ void __launch_bounds__(TPB, 3)
gtp_main(const float* __restrict__ x1, const float* __restrict__ x2,
         const float* __restrict__ W1, const float* __restrict__ W2,
         const float* __restrict__ Y,  const float* __restrict__ Yw,
         float* __restrict__ out, int nrows)
{
    __shared__ u64 sW1[DC * 16];     // W pairs (W[d,+m], W[d,-m]), padded stride 16
    __shared__ u64 sW2[DC * 16];
    __shared__ u64 sP [RBC * 16];    // (P, P)
    __shared__ u64 sPw[RBC * 16];    // (P*qw, P*qw)
    __shared__ u64 sAng[RAC * 6];    // m=0..4: (sqrt2*cos(m a), sqrt2*sin(m a)); m=0 -> (1,0)

    const int tid = threadIdx.x;
    const float SQ2  = 1.41421356237309505f;
    const float ISQ2 = 0.70710678118654752f;

    // ---- build tables (each CTA, from global inputs; all exact divisions of Y/Yw) ----
    for (int k = tid; k < DC * NP; k += TPB) {
        int d = k / NP, p = k % NP;
        int l = (p >= 10) ? 4 : (p >= 6) ? 3 : (p >= 3) ? 2 : (p >= 1) ? 1 : 0;
        int m = p - l * (l + 1) / 2;
        int ip = l * l + l + m, in_ = ip - 2 * m;
        sW1[d * 16 + p] = pk(W1[d * SC + ip], W1[d * SC + in_]);
        sW2[d * 16 + p] = pk(W2[d * SC + ip], W2[d * SC + in_]);
    }
    for (int d = tid; d < DC; d += TPB) { sW1[d * 16 + 15] = 0ull; sW2[d * 16 + 15] = 0ull; }

    for (int t = tid; t < RBC * NP; t += TPB) {
        int b = t / NP, p = t % NP;
        int l = (p >= 10) ? 4 : (p >= 6) ? 3 : (p >= 3) ? 2 : (p >= 1) ? 1 : 0;
        int m = p - l * (l + 1) / 2;
        int ip = l * l + l + m;
        float y0 = Y[(b * RAC) * SC + ip];                 // a = 0 column: ang=1 (m=0) or sqrt2 (m>0)
        float P  = (m > 0) ? y0 * ISQ2 : y0;
        float qw = Yw[(b * RAC) * SC] / Y[(b * RAC) * SC]; // Y[b,0,0] = const > 0
        sP [b * 16 + p] = pk(P, P);
        float pw = P * qw;
        sPw[b * 16 + p] = pk(pw, pw);
    }

    for (int t = tid; t < RAC * 5; t += TPB) {
        int a = t / 5, m = t % 5;
        if (m == 0) {
            sAng[a * 6] = pk(1.0f, 0.0f);
        } else {
            const int b0 = RBC / 2;                        // mid Gauss node, sin(beta)~1
            int ip = m * m + 2 * m, in_ = m * m;
            float den = Y[(b0 * RAC) * SC + ip];           // sqrt2 * P[m,m](x_b0)
            float ac2 = SQ2 * Y[(b0 * RAC + a) * SC + ip ] / den;
            float as2 = SQ2 * Y[(b0 * RAC + a) * SC + in_] / den;
            sAng[a * 6 + m] = pk(ac2, as2);
        }
    }
    __syncthreads();

    const long long r = (long long)blockIdx.x * TPB + tid;   // one row per thread
    if (r >= nrows) return;

    // ---- projection: c_pair[p] = sum_d x[d] * (W[d,+m], W[d,-m]) ----
    u64 c1p[NP], c2p[NP];
    #pragma unroll
    for (int p = 0; p < NP; p++) { c1p[p] = 0ull; c2p[p] = 0ull; }

    const float4* xa = (const float4*)(x1 + r * DC);
    const float4* xb = (const float4*)(x2 + r * DC);
    #pragma unroll 4
    for (int d4 = 0; d4 < DC / 4; d4++) {
        float4 A = xa[d4], B = xb[d4];
        float av[4] = {A.x, A.y, A.z, A.w};
        float bv[4] = {B.x, B.y, B.z, B.w};
        #pragma unroll
        for (int j = 0; j < 4; j++) {
            u64 xd1 = pk(av[j], av[j]);
            u64 xd2 = pk(bv[j], bv[j]);
            const u64* w1 = &sW1[(d4 * 4 + j) * 16];
            const u64* w2 = &sW2[(d4 * 4 + j) * 16];
            #pragma unroll
            for (int p = 0; p < NP; p++) {
                c1p[p] = fma2(xd1, w1[p], c1p[p]);
                c2p[p] = fma2(xd2, w2[p], c2p[p]);
            }
        }
    }

    // ---- sphere: for each beta node, F -> grid product -> H -> back-project ----
    u64 accp[NP];
    #pragma unroll
    for (int p = 0; p < NP; p++) accp[p] = 0ull;

    #pragma unroll 1
    for (int b = 0; b < RBC; b++) {
        const u64* Pb  = &sP [b * 16];
        const u64* Pwb = &sPw[b * 16];

        u64 F1[5], F2[5];
        #pragma unroll
        for (int m = 0; m < 5; m++) { F1[m] = 0ull; F2[m] = 0ull; }
        #pragma unroll
        for (int p = 0; p < NP; p++) {
            const int m = c_m[p];
            u64 P = Pb[p];
            F1[m] = fma2(c1p[p], P, F1[m]);
            F2[m] = fma2(c2p[p], P, F2[m]);
        }

        u64 H[5];
        #pragma unroll
        for (int m = 0; m < 5; m++) H[m] = 0ull;

        #pragma unroll
        for (int a = 0; a < RAC; a++) {
            const u64* An = &sAng[a * 6];
            u64 am[5];
            #pragma unroll
            for (int m = 0; m < 5; m++) am[m] = An[m];
            u64 g1 = 0ull, g2 = 0ull;
            #pragma unroll
            for (int m = 0; m < 5; m++) {
                g1 = fma2(F1[m], am[m], g1);
                g2 = fma2(F2[m], am[m], g2);
            }
            float l1, h1, l2, h2;
            unpk(g1, l1, h1); unpk(g2, l2, h2);
            float h = (l1 + h1) * (l2 + h2);      // pointwise product on the grid
            u64 hd = pk(h, h);
            #pragma unroll
            for (int m = 0; m < 5; m++) H[m] = fma2(hd, am[m], H[m]);
        }

        #pragma unroll
        for (int p = 0; p < NP; p++) {
            accp[p] = fma2(H[c_m[p]], Pwb[p], accp[p]);
        }
    }

    // ---- output ----
    float* o = out + r * SC;
    #pragma unroll
    for (int p = 0; p < NP; p++) {
        float lo, hi; unpk(accp[p], lo, hi);
        o[c_ip[p]] = lo;
        if (c_m[p] > 0) o[c_in[p]] = hi;
    }
}

extern "C" void kernel_launch(void* const* d_in, const int* in_sizes, int n_in,
                              void* d_out, int out_size) {
    const float* x1 = (const float*)d_in[0];
    const float* x2 = (const float*)d_in[1];
    const float* W1 = (const float*)d_in[2];
    const float* W2 = (const float*)d_in[3];
    const float* Y  = (const float*)d_in[4];
    const float* Yw = (const float*)d_in[5];
    float* out = (float*)d_out;

    const int nrows = in_sizes[0] / DC;            // 131072
    const int grid  = (nrows + TPB - 1) / TPB;     // 1024

    gtp_main<<<grid, TPB>>>(x1, x2, W1, W2, Y, Yw, out, nrows);
}